// round 3
// baseline (speedup 1.0000x reference)
#include <cuda_runtime.h>
#include <math.h>

#define LSEQ 2048
#define DMODEL 1024
#define NSTATE 32
#define VOCAB 32000
#define CTOT (DMODEL * NSTATE)  // 32768

// ---------------- scratch (no allocations allowed) ----------------
__device__ float g_xin[LSEQ * DMODEL];
__device__ float g_z[LSEQ * DMODEL];
__device__ float g_delta[LSEQ * DMODEL];
__device__ float g_Bseq[LSEQ * NSTATE];
__device__ float g_Cseq[LSEQ * NSTATE];
__device__ float g_u[LSEQ * DMODEL];
__device__ float g_ln[LSEQ * DMODEL];
__device__ float g_mid[LSEQ * DMODEL];
__device__ float g_a[(size_t)LSEQ * CTOT];   // 256 MB: A_bar tree
__device__ float g_b[(size_t)LSEQ * CTOT];   // 256 MB: B_bar tree / h

// ---------------- generic tiled SGEMM: C = A(MxK) * B(NxK)^T + bias ----------------
// MODE 0: plain (+bias)
// MODE 1: split epilogue: col<DMODEL -> C (x_in); col>=DMODEL -> C2 = sigmoid (z)
// MODE 2: softplus(v + bias + bias2)  (delta)
template <int MODE>
__global__ __launch_bounds__(256) void sgemm_kernel(
    const float* __restrict__ A, const float* __restrict__ B,
    const float* __restrict__ bias, const float* __restrict__ bias2,
    float* __restrict__ C, float* __restrict__ C2,
    int M, int N, int K) {
  __shared__ float As[16][128];
  __shared__ float Bs[16][128];
  const int tid = threadIdx.x;
  const int tx = tid & 15;
  const int ty = tid >> 4;
  const int rowA0 = blockIdx.y * 128;
  const int colB0 = blockIdx.x * 128;

  float acc[8][8];
#pragma unroll
  for (int i = 0; i < 8; i++)
#pragma unroll
    for (int j = 0; j < 8; j++) acc[i][j] = 0.f;

  const int lr = tid >> 2;
  const int lc = (tid & 3) * 4;

  for (int k0 = 0; k0 < K; k0 += 16) {
#pragma unroll
    for (int i = 0; i < 2; i++) {
      int r = lr + i * 64;
      float4 va = *(const float4*)(A + (size_t)(rowA0 + r) * K + k0 + lc);
      As[lc + 0][r] = va.x; As[lc + 1][r] = va.y;
      As[lc + 2][r] = va.z; As[lc + 3][r] = va.w;
      float4 vb = *(const float4*)(B + (size_t)(colB0 + r) * K + k0 + lc);
      Bs[lc + 0][r] = vb.x; Bs[lc + 1][r] = vb.y;
      Bs[lc + 2][r] = vb.z; Bs[lc + 3][r] = vb.w;
    }
    __syncthreads();
#pragma unroll
    for (int kk = 0; kk < 16; kk++) {
      float4 a0 = *(const float4*)&As[kk][ty * 8];
      float4 a1 = *(const float4*)&As[kk][ty * 8 + 4];
      float4 b0 = *(const float4*)&Bs[kk][tx * 8];
      float4 b1 = *(const float4*)&Bs[kk][tx * 8 + 4];
      float av[8] = {a0.x, a0.y, a0.z, a0.w, a1.x, a1.y, a1.z, a1.w};
      float bv[8] = {b0.x, b0.y, b0.z, b0.w, b1.x, b1.y, b1.z, b1.w};
#pragma unroll
      for (int i = 0; i < 8; i++)
#pragma unroll
        for (int j = 0; j < 8; j++)
          acc[i][j] = fmaf(av[i], bv[j], acc[i][j]);
    }
    __syncthreads();
  }

#pragma unroll
  for (int i = 0; i < 8; i++) {
    int row = rowA0 + ty * 8 + i;
#pragma unroll
    for (int j = 0; j < 8; j++) {
      int col = colB0 + tx * 8 + j;
      float v = acc[i][j] + bias[col];
      if (MODE == 0) {
        C[(size_t)row * N + col] = v;
      } else if (MODE == 1) {
        if (col < DMODEL)
          C[(size_t)row * DMODEL + col] = v;
        else
          C2[(size_t)row * DMODEL + (col - DMODEL)] = 1.f / (1.f + expf(-v));
      } else {
        v += bias2[col];
        C[(size_t)row * N + col] = (v > 20.f) ? v : log1pf(expf(v));
      }
    }
  }
}

// ---------------- B_seq / C_seq ----------------
__global__ __launch_bounds__(256) void bc_seq_kernel(
    const float* __restrict__ xin, const float* __restrict__ binj,
    const float* __restrict__ cinj,
    const float* __restrict__ W_B, const float* __restrict__ W_C,
    const float* __restrict__ W_bi, const float* __restrict__ W_ci,
    float* __restrict__ Bseq, float* __restrict__ Cseq) {
  __shared__ float sx[DMODEL], sb[DMODEL], sc[DMODEL];
  const int l = blockIdx.x;
  for (int i = threadIdx.x; i < DMODEL; i += 256) {
    sx[i] = xin[(size_t)l * DMODEL + i];
    sb[i] = binj[(size_t)l * DMODEL + i];
    sc[i] = cinj[(size_t)l * DMODEL + i];
  }
  __syncthreads();
  const int n = threadIdx.x >> 3;
  const int part = threadIdx.x & 7;
  float s1 = 0.f, s2 = 0.f, s3 = 0.f, s4 = 0.f;
  const float* wb = W_B + (size_t)n * DMODEL;
  const float* wc = W_C + (size_t)n * DMODEL;
  const float* wbi = W_bi + (size_t)n * DMODEL;
  const float* wci = W_ci + (size_t)n * DMODEL;
#pragma unroll 8
  for (int i = 0; i < 128; i++) {
    int k = part + i * 8;
    float xv = sx[k], bv = sb[k], cv = sc[k];
    s1 = fmaf(xv, wb[k], s1);
    s2 = fmaf(bv, wbi[k], s2);
    s3 = fmaf(xv, wc[k], s3);
    s4 = fmaf(cv, wci[k], s4);
  }
#pragma unroll
  for (int off = 4; off; off >>= 1) {
    s1 += __shfl_down_sync(0xffffffffu, s1, off, 8);
    s2 += __shfl_down_sync(0xffffffffu, s2, off, 8);
    s3 += __shfl_down_sync(0xffffffffu, s3, off, 8);
    s4 += __shfl_down_sync(0xffffffffu, s4, off, 8);
  }
  if (part == 0) {
    Bseq[(size_t)l * NSTATE + n] = s1 * (1.f + tanhf(s2));
    Cseq[(size_t)l * NSTATE + n] = s3 * (1.f + tanhf(s4));
  }
}

// ---------------- build A_bar / B_bar arrays: layout [t][d*32+n] ----------------
__global__ __launch_bounds__(256) void init_ab_kernel(
    const float* __restrict__ log_A, const float* __restrict__ delta,
    const float* __restrict__ Bseq, float* __restrict__ ga,
    float* __restrict__ gb) {
  size_t idx = (size_t)blockIdx.x * 256 + threadIdx.x;
  int c = (int)(idx & (CTOT - 1));
  int t = (int)(idx >> 15);
  int d = c >> 5, n = c & 31;
  float A = -expf(log_A[c]);
  float dt = delta[(size_t)t * DMODEL + d];
  float a = expf(dt * A);
  float b = (a - 1.f) * (1.f / A) * Bseq[t * NSTATE + n];
  ga[idx] = a;
  gb[idx] = b;
}

// ---------------- exact reference upsweep: ar = a[r]*a[l]; br = ar*b[l] + b[r] ----------------
__global__ __launch_bounds__(256) void upsweep_kernel(
    float* __restrict__ ga, float* __restrict__ gb, int step) {
  size_t idx = (size_t)blockIdx.x * 256 + threadIdx.x;
  int c = (int)(idx & (CTOT - 1));
  int pair = (int)(idx >> 15);
  int l = pair * 2 * step + step - 1;
  int r = l + step;
  size_t li = (size_t)l * CTOT + c, ri = (size_t)r * CTOT + c;
  float ar = ga[ri] * ga[li];
  float br = ar * gb[li] + gb[ri];
  ga[ri] = ar;
  gb[ri] = br;
}

// ---------------- root reset: a[p-1]=1, b[p-1]=0 ----------------
__global__ __launch_bounds__(256) void root_kernel(float* __restrict__ ga,
                                                   float* __restrict__ gb) {
  int c = blockIdx.x * 256 + threadIdx.x;
  size_t i = (size_t)(LSEQ - 1) * CTOT + c;
  ga[i] = 1.f;
  gb[i] = 0.f;
}

// ---------------- exact reference downsweep ----------------
__global__ __launch_bounds__(256) void downsweep_kernel(
    float* __restrict__ ga, float* __restrict__ gb, int step) {
  size_t idx = (size_t)blockIdx.x * 256 + threadIdx.x;
  int c = (int)(idx & (CTOT - 1));
  int pair = (int)(idx >> 15);
  int l = pair * 2 * step + step - 1;
  int r = l + step;
  size_t li = (size_t)l * CTOT + c, ri = (size_t)r * CTOT + c;
  float al = ga[li], bl = gb[li];
  float ar = ga[ri], br = gb[ri];
  float nb = ar * bl + br;
  ga[li] = ar;
  ga[ri] = ar * al;
  gb[li] = nb;
  gb[ri] = nb;
}

// ---------------- y = einsum(h, C_seq); u = y*z + x_in (warp per (t,d)) ----------------
__global__ __launch_bounds__(256) void ssm_out_kernel(
    const float* __restrict__ gb, const float* __restrict__ Cseq,
    const float* __restrict__ z, const float* __restrict__ xin,
    float* __restrict__ u) {
  size_t gw = ((size_t)blockIdx.x * 256 + threadIdx.x) >> 5;  // t*DMODEL + d
  int lane = threadIdx.x & 31;
  int t = (int)(gw >> 10);
  int d = (int)(gw & (DMODEL - 1));
  float v = gb[(size_t)t * CTOT + d * NSTATE + lane] * Cseq[t * NSTATE + lane];
#pragma unroll
  for (int off = 16; off; off >>= 1) v += __shfl_xor_sync(0xffffffffu, v, off);
  if (lane == 0) u[gw] = fmaf(v, z[gw], xin[gw]);
}

// ---------------- LayerNorm ----------------
__global__ __launch_bounds__(256) void layernorm_kernel(
    const float* __restrict__ u, const float* __restrict__ g,
    const float* __restrict__ beta, float* __restrict__ o) {
  const int l = blockIdx.x;
  const float* row = u + (size_t)l * DMODEL;
  float s = 0.f, s2 = 0.f;
  for (int i = threadIdx.x; i < DMODEL; i += 256) {
    float v = row[i];
    s += v;
    s2 += v * v;
  }
#pragma unroll
  for (int off = 16; off; off >>= 1) {
    s += __shfl_xor_sync(0xffffffffu, s, off);
    s2 += __shfl_xor_sync(0xffffffffu, s2, off);
  }
  __shared__ float shs[8], shs2[8];
  const int w = threadIdx.x >> 5;
  if ((threadIdx.x & 31) == 0) { shs[w] = s; shs2[w] = s2; }
  __syncthreads();
  if (threadIdx.x < 32) {
    s = (threadIdx.x < 8) ? shs[threadIdx.x] : 0.f;
    s2 = (threadIdx.x < 8) ? shs2[threadIdx.x] : 0.f;
#pragma unroll
    for (int off = 4; off; off >>= 1) {
      s += __shfl_xor_sync(0xffffffffu, s, off);
      s2 += __shfl_xor_sync(0xffffffffu, s2, off);
    }
    if (threadIdx.x == 0) { shs[0] = s; shs2[0] = s2; }
  }
  __syncthreads();
  const float mu = shs[0] * (1.f / DMODEL);
  const float var = shs2[0] * (1.f / DMODEL) - mu * mu;
  const float rstd = rsqrtf(var + 1e-5f);
  for (int i = threadIdx.x; i < DMODEL; i += 256)
    o[(size_t)l * DMODEL + i] = (row[i] - mu) * rstd * g[i] + beta[i];
}

// ---------------- launch ----------------
extern "C" void kernel_launch(void* const* d_in, const int* in_sizes, int n_in,
                              void* d_out, int out_size) {
  const float* x         = (const float*)d_in[0];
  const float* b_inject  = (const float*)d_in[1];
  const float* c_inject  = (const float*)d_in[2];
  const float* W_in      = (const float*)d_in[3];
  const float* b_in      = (const float*)d_in[4];
  const float* log_A     = (const float*)d_in[5];
  const float* W_B       = (const float*)d_in[6];
  const float* W_C       = (const float*)d_in[7];
  const float* W_delta   = (const float*)d_in[8];
  const float* b_delta   = (const float*)d_in[9];
  const float* delta_bias= (const float*)d_in[10];
  const float* W_bi      = (const float*)d_in[11];
  const float* W_ci      = (const float*)d_in[12];
  const float* ln_g      = (const float*)d_in[13];
  const float* ln_b      = (const float*)d_in[14];
  const float* W_out     = (const float*)d_in[15];
  const float* b_out     = (const float*)d_in[16];
  const float* W_vocab   = (const float*)d_in[17];
  const float* b_vocab   = (const float*)d_in[18];
  float* out = (float*)d_out;

  void* p;
  cudaGetSymbolAddress(&p, g_xin);   float* xin   = (float*)p;
  cudaGetSymbolAddress(&p, g_z);     float* zbuf  = (float*)p;
  cudaGetSymbolAddress(&p, g_delta); float* delta = (float*)p;
  cudaGetSymbolAddress(&p, g_Bseq);  float* Bseq  = (float*)p;
  cudaGetSymbolAddress(&p, g_Cseq);  float* Cseq  = (float*)p;
  cudaGetSymbolAddress(&p, g_u);     float* ubuf  = (float*)p;
  cudaGetSymbolAddress(&p, g_ln);    float* lnbuf = (float*)p;
  cudaGetSymbolAddress(&p, g_mid);   float* mid   = (float*)p;
  cudaGetSymbolAddress(&p, g_a);     float* ga    = (float*)p;
  cudaGetSymbolAddress(&p, g_b);     float* gb    = (float*)p;

  // 1. xz = x @ W_in^T + b_in -> x_in, z=sigmoid
  sgemm_kernel<1><<<dim3(2 * DMODEL / 128, LSEQ / 128), 256>>>(
      x, W_in, b_in, nullptr, xin, zbuf, LSEQ, 2 * DMODEL, DMODEL);
  // 2. delta = softplus(x_in @ W_delta^T + b_delta + delta_bias)
  sgemm_kernel<2><<<dim3(DMODEL / 128, LSEQ / 128), 256>>>(
      xin, W_delta, b_delta, delta_bias, delta, nullptr, LSEQ, DMODEL, DMODEL);
  // 3. B_seq / C_seq
  bc_seq_kernel<<<LSEQ, 256>>>(xin, b_inject, c_inject, W_B, W_C, W_bi, W_ci,
                               Bseq, Cseq);
  // 4. build A_bar, B_bar
  init_ab_kernel<<<(size_t)LSEQ * CTOT / 256, 256>>>(log_A, delta, Bseq, ga, gb);
  // 5. exact reference tree scan
  for (int step = 1; step < LSEQ; step <<= 1) {
    int npairs = LSEQ / (2 * step);
    upsweep_kernel<<<(size_t)npairs * CTOT / 256, 256>>>(ga, gb, step);
  }
  root_kernel<<<CTOT / 256, 256>>>(ga, gb);
  for (int step = LSEQ >> 1; step >= 1; step >>= 1) {
    int npairs = LSEQ / (2 * step);
    downsweep_kernel<<<(size_t)npairs * CTOT / 256, 256>>>(ga, gb, step);
  }
  // 6. y = einsum(h, C_seq); u = y*z + x_in
  ssm_out_kernel<<<(size_t)LSEQ * DMODEL * 32 / 256, 256>>>(gb, Cseq, zbuf, xin,
                                                            ubuf);
  // 7. LayerNorm
  layernorm_kernel<<<LSEQ, 256>>>(ubuf, ln_g, ln_b, lnbuf);
  // 8. mid = ln @ W_out^T + b_out
  sgemm_kernel<0><<<dim3(DMODEL / 128, LSEQ / 128), 256>>>(
      lnbuf, W_out, b_out, nullptr, mid, nullptr, LSEQ, DMODEL, DMODEL);
  // 9. logits = mid @ W_vocab^T + b_vocab  (dominant)
  sgemm_kernel<0><<<dim3(VOCAB / 128, LSEQ / 128), 256>>>(
      mid, W_vocab, b_vocab, nullptr, out, nullptr, LSEQ, VOCAB, DMODEL);
}